// round 2
// baseline (speedup 1.0000x reference)
#include <cuda_runtime.h>
#include <math.h>

#define NB 4
#define CIN 256
#define CO 256
#define HDIM 56
#define WDIM 56
#define HW 3136
#define NCOL 12544     // NB*HW
#define NHEAD 2
#define HD 128
#define EPS 1e-5f
#define SEH 16

// ---------------- scratch (device globals, no allocation) ----------------
__device__ float g_qt[NCOL * CO];   // [n][c] transposed
__device__ float g_kt[NCOL * CO];
__device__ float g_vt[NCOL * CO];
__device__ float g_y1[NB * CO * HW]; // after attn + BN1 + relu, channel-major
__device__ float g_y2[NB * CO * HW]; // after agg conv + BN2, channel-major
__device__ float g_s [NB * SEH * HW];
__device__ float g_p [NB * SEH];
__device__ float g_g [NB * SEH];

// ---------------- GEMM: q/k/v = W @ x, write TRANSPOSED [n][256] ----------------
__global__ void gemm_qkv_kernel(const float* __restrict__ Wq,
                                const float* __restrict__ Wk,
                                const float* __restrict__ Wv,
                                const float* __restrict__ x) {
    const float* Wm = (blockIdx.z == 0) ? Wq : (blockIdx.z == 1 ? Wk : Wv);
    float* outp = (blockIdx.z == 0) ? g_qt : (blockIdx.z == 1 ? g_kt : g_vt);

    __shared__ float As[64][17];  // [o_local][c_local], padded
    __shared__ float Bs[16][64];  // [c_local][n_local]

    int tid = threadIdx.x;
    int tx = tid & 15, ty = tid >> 4;
    int o0 = blockIdx.y * 64;
    int n0 = blockIdx.x * 64;        // 3136 % 64 == 0: tile never crosses batch
    int bb = n0 / HW;
    int hw0 = n0 % HW;
    const float* xb = x + (size_t)bb * CIN * HW + hw0;

    int arow = tid >> 2, aseg = tid & 3;
    int brow = tid >> 4, bseg = tid & 15;

    float acc[4][4];
#pragma unroll
    for (int i = 0; i < 4; i++)
#pragma unroll
        for (int j = 0; j < 4; j++) acc[i][j] = 0.f;

    for (int k0 = 0; k0 < CIN; k0 += 16) {
        float4 av = *(const float4*)&Wm[(o0 + arow) * CIN + k0 + aseg * 4];
        float4 bv = *(const float4*)&xb[(size_t)(k0 + brow) * HW + bseg * 4];
        __syncthreads();
        As[arow][aseg * 4 + 0] = av.x;
        As[arow][aseg * 4 + 1] = av.y;
        As[arow][aseg * 4 + 2] = av.z;
        As[arow][aseg * 4 + 3] = av.w;
        *(float4*)&Bs[brow][bseg * 4] = bv;
        __syncthreads();
#pragma unroll
        for (int c = 0; c < 16; c++) {
            float a0 = As[ty * 4 + 0][c];
            float a1 = As[ty * 4 + 1][c];
            float a2 = As[ty * 4 + 2][c];
            float a3 = As[ty * 4 + 3][c];
            float4 b4 = *(float4*)&Bs[c][tx * 4];
            acc[0][0] += a0 * b4.x; acc[0][1] += a0 * b4.y; acc[0][2] += a0 * b4.z; acc[0][3] += a0 * b4.w;
            acc[1][0] += a1 * b4.x; acc[1][1] += a1 * b4.y; acc[1][2] += a1 * b4.z; acc[1][3] += a1 * b4.w;
            acc[2][0] += a2 * b4.x; acc[2][1] += a2 * b4.y; acc[2][2] += a2 * b4.z; acc[2][3] += a2 * b4.w;
            acc[3][0] += a3 * b4.x; acc[3][1] += a3 * b4.y; acc[3][2] += a3 * b4.z; acc[3][3] += a3 * b4.w;
        }
    }
    // transposed store: out[n][o], 4 consecutive o per float4
#pragma unroll
    for (int j = 0; j < 4; j++) {
        float4 v;
        v.x = acc[0][j]; v.y = acc[1][j]; v.z = acc[2][j]; v.w = acc[3][j];
        *(float4*)&outp[(size_t)(n0 + tx * 4 + j) * CO + o0 + ty * 4] = v;
    }
}

// ---------------- attention: warp per (b, head, h, w) ----------------
__global__ void attn_kernel(const float* __restrict__ rel_h,
                            const float* __restrict__ rel_w,
                            const float* __restrict__ g1, const float* __restrict__ b1,
                            const float* __restrict__ m1, const float* __restrict__ v1) {
    int wid = blockIdx.x * 8 + (threadIdx.x >> 5);
    int lane = threadIdx.x & 31;
    int b = wid / (NHEAD * HW);
    int r = wid % (NHEAD * HW);
    int nh = r / HW;
    int hw = r % HW;
    int h = hw / WDIM, w = hw % WDIM;

    const float4 q4 = *(const float4*)&g_qt[(size_t)(b * HW + hw) * CO + nh * HD + lane * 4];
    const float* rel = nh ? rel_w : rel_h;   // [c][tap], size 128*5

    // bias[t] = sum_c q[c] * rel[c][t]
    float bias[5];
#pragma unroll
    for (int t = 0; t < 5; t++) {
        int c = lane * 4;
        float p = q4.x * rel[(c + 0) * 5 + t] + q4.y * rel[(c + 1) * 5 + t]
                + q4.z * rel[(c + 2) * 5 + t] + q4.w * rel[(c + 3) * 5 + t];
#pragma unroll
        for (int m = 16; m; m >>= 1) p += __shfl_xor_sync(0xffffffffu, p, m);
        bias[t] = p;
    }

    float sc[25];
#pragma unroll
    for (int ki = 0; ki < 5; ki++) {
        int hh = h + ki - 2;
#pragma unroll
        for (int kj = 0; kj < 5; kj++) {
            int ww = w + kj - 2;
            bool inb = (hh >= 0 && hh < HDIM && ww >= 0 && ww < WDIM);
            float p = 0.f;
            if (inb) {
                const float4 k4 = *(const float4*)
                    &g_kt[(size_t)(b * HW + hh * WDIM + ww) * CO + nh * HD + lane * 4];
                p = q4.x * k4.x + q4.y * k4.y + q4.z * k4.z + q4.w * k4.w;
            }
#pragma unroll
            for (int m = 16; m; m >>= 1) p += __shfl_xor_sync(0xffffffffu, p, m);
            sc[ki * 5 + kj] = (p + bias[nh ? kj : ki]) * 0.08838834764831845f;
        }
    }

    float mx = sc[0];
#pragma unroll
    for (int i = 1; i < 25; i++) mx = fmaxf(mx, sc[i]);
    float sum = 0.f;
#pragma unroll
    for (int i = 0; i < 25; i++) { sc[i] = __expf(sc[i] - mx); sum += sc[i]; }
    float inv = 1.f / sum;

    float4 acc = make_float4(0.f, 0.f, 0.f, 0.f);
#pragma unroll
    for (int ki = 0; ki < 5; ki++) {
        int hh = h + ki - 2;
#pragma unroll
        for (int kj = 0; kj < 5; kj++) {
            int ww = w + kj - 2;
            if (hh >= 0 && hh < HDIM && ww >= 0 && ww < WDIM) {
                const float4 v4 = *(const float4*)
                    &g_vt[(size_t)(b * HW + hh * WDIM + ww) * CO + nh * HD + lane * 4];
                float a = sc[ki * 5 + kj];
                acc.x += a * v4.x; acc.y += a * v4.y; acc.z += a * v4.z; acc.w += a * v4.w;
            }
        }
    }

    float av[4] = {acc.x * inv, acc.y * inv, acc.z * inv, acc.w * inv};
#pragma unroll
    for (int i = 0; i < 4; i++) {
        int ch = nh * HD + lane * 4 + i;
        float scl = g1[ch] * rsqrtf(v1[ch] + EPS);
        float val = (av[i] - m1[ch]) * scl + b1[ch];
        g_y1[(size_t)b * CO * HW + (size_t)ch * HW + hw] = fmaxf(val, 0.f);
    }
}

// ---------------- agg GEMM: y2 = BN2(agg_W @ y1), channel-major output -------
__global__ void gemm_agg_kernel(const float* __restrict__ Wm,
                                const float* __restrict__ g2, const float* __restrict__ b2,
                                const float* __restrict__ m2, const float* __restrict__ v2) {
    __shared__ float As[64][17];
    __shared__ float Bs[16][64];

    int tid = threadIdx.x;
    int tx = tid & 15, ty = tid >> 4;
    int o0 = blockIdx.y * 64;
    int n0 = blockIdx.x * 64;
    int bb = n0 / HW;
    int hw0 = n0 % HW;
    const float* xb = g_y1 + (size_t)bb * CO * HW + hw0;

    int arow = tid >> 2, aseg = tid & 3;
    int brow = tid >> 4, bseg = tid & 15;

    float acc[4][4];
#pragma unroll
    for (int i = 0; i < 4; i++)
#pragma unroll
        for (int j = 0; j < 4; j++) acc[i][j] = 0.f;

    for (int k0 = 0; k0 < CO; k0 += 16) {
        float4 av = *(const float4*)&Wm[(o0 + arow) * CO + k0 + aseg * 4];
        float4 bv = *(const float4*)&xb[(size_t)(k0 + brow) * HW + bseg * 4];
        __syncthreads();
        As[arow][aseg * 4 + 0] = av.x;
        As[arow][aseg * 4 + 1] = av.y;
        As[arow][aseg * 4 + 2] = av.z;
        As[arow][aseg * 4 + 3] = av.w;
        *(float4*)&Bs[brow][bseg * 4] = bv;
        __syncthreads();
#pragma unroll
        for (int c = 0; c < 16; c++) {
            float a0 = As[ty * 4 + 0][c];
            float a1 = As[ty * 4 + 1][c];
            float a2 = As[ty * 4 + 2][c];
            float a3 = As[ty * 4 + 3][c];
            float4 b4 = *(float4*)&Bs[c][tx * 4];
            acc[0][0] += a0 * b4.x; acc[0][1] += a0 * b4.y; acc[0][2] += a0 * b4.z; acc[0][3] += a0 * b4.w;
            acc[1][0] += a1 * b4.x; acc[1][1] += a1 * b4.y; acc[1][2] += a1 * b4.z; acc[1][3] += a1 * b4.w;
            acc[2][0] += a2 * b4.x; acc[2][1] += a2 * b4.y; acc[2][2] += a2 * b4.z; acc[2][3] += a2 * b4.w;
            acc[3][0] += a3 * b4.x; acc[3][1] += a3 * b4.y; acc[3][2] += a3 * b4.z; acc[3][3] += a3 * b4.w;
        }
    }
#pragma unroll
    for (int i = 0; i < 4; i++) {
        int o = o0 + ty * 4 + i;
        float scl = g2[o] * rsqrtf(v2[o] + EPS);
        float bo = b2[o] - m2[o] * scl;
        float4 v;
        v.x = acc[i][0] * scl + bo;
        v.y = acc[i][1] * scl + bo;
        v.z = acc[i][2] * scl + bo;
        v.w = acc[i][3] * scl + bo;
        *(float4*)&g_y2[(size_t)bb * CO * HW + (size_t)o * HW + hw0 + tx * 4] = v;
    }
}

// ---------------- zero p accumulator (graph-replay safe) ----------------
__global__ void zero_p_kernel() {
    if (threadIdx.x < NB * SEH) g_p[threadIdx.x] = 0.f;
}

// ---------------- SE stage 1: s = relu(BN(se_Win @ y2)), partial pooling -----
__global__ void se1_kernel(const float* __restrict__ Win,
                           const float* __restrict__ gin, const float* __restrict__ bin,
                           const float* __restrict__ min_, const float* __restrict__ vin) {
    __shared__ float Ws[SEH * CO];
    int tid = threadIdx.x;
    for (int i = tid; i < SEH * CO; i += 256) Ws[i] = Win[i];
    __syncthreads();

    int o = tid >> 4;          // 0..15 output channel
    int ng = tid & 15;         // 0..15 -> 4 columns each (64 n per block)
    int n0 = blockIdx.x * 64;  // 3136 % 64 == 0
    int bb = n0 / HW;
    int hw0 = n0 % HW;
    const float* yb = g_y2 + (size_t)bb * CO * HW + hw0 + ng * 4;

    float4 acc = make_float4(0.f, 0.f, 0.f, 0.f);
    for (int c = 0; c < CO; c++) {
        float wv = Ws[o * CO + c];
        float4 xv = *(const float4*)&yb[(size_t)c * HW];
        acc.x += wv * xv.x; acc.y += wv * xv.y; acc.z += wv * xv.z; acc.w += wv * xv.w;
    }
    float scl = gin[o] * rsqrtf(vin[o] + EPS);
    float bo = bin[o] - min_[o] * scl;
    float4 sv;
    sv.x = fmaxf(acc.x * scl + bo, 0.f);
    sv.y = fmaxf(acc.y * scl + bo, 0.f);
    sv.z = fmaxf(acc.z * scl + bo, 0.f);
    sv.w = fmaxf(acc.w * scl + bo, 0.f);
    *(float4*)&g_s[(size_t)bb * SEH * HW + (size_t)o * HW + hw0 + ng * 4] = sv;

    float psum = sv.x + sv.y + sv.z + sv.w;
#pragma unroll
    for (int m = 8; m; m >>= 1) psum += __shfl_xor_sync(0xffffffffu, psum, m);
    if (ng == 0) atomicAdd(&g_p[bb * SEH + o], psum);
}

// ---------------- SE stage 2: gates ----------------
__global__ void se2_kernel(const float* __restrict__ fc1, const float* __restrict__ fc2) {
    int tid = threadIdx.x;
    if (tid < NB * SEH) {
        int bb = tid >> 4, i = tid & 15;
        float hsum = 0.f;
#pragma unroll
        for (int j = 0; j < SEH; j++) hsum += (g_p[bb * SEH + j] * (1.f / HW)) * fc1[j];
        float hid = fmaxf(hsum, 0.f);
        g_g[tid] = 1.f / (1.f + __expf(-(hid * fc2[i])));
    }
}

// ---------------- SE stage 3: out = BN(se_Wout @ (s * g)) ----------------
__global__ void se3_kernel(const float* __restrict__ Wout,
                           const float* __restrict__ gout, const float* __restrict__ bout,
                           const float* __restrict__ mout, const float* __restrict__ vout,
                           float* __restrict__ out) {
    __shared__ float sjs[SEH][16];  // [j][n_local]
    int tid = threadIdx.x;          // 256 threads = 256 output channels
    int n0 = blockIdx.x * 16;       // 3136 % 16 == 0
    int bb = n0 / HW;
    int hw0 = n0 % HW;

    int j = tid >> 4, nn = tid & 15;
    sjs[j][nn] = g_s[(size_t)bb * SEH * HW + (size_t)j * HW + hw0 + nn] * g_g[bb * SEH + j];
    __syncthreads();

    int o = tid;
    float wreg[SEH];
#pragma unroll
    for (int jj = 0; jj < SEH; jj++) wreg[jj] = Wout[o * SEH + jj];
    float scl = gout[o] * rsqrtf(vout[o] + EPS);
    float bo = bout[o] - mout[o] * scl;
    float* op = out + (size_t)bb * CO * HW + (size_t)o * HW + hw0;
#pragma unroll
    for (int nq = 0; nq < 4; nq++) {
        float4 a = make_float4(0.f, 0.f, 0.f, 0.f);
#pragma unroll
        for (int jj = 0; jj < SEH; jj++) {
            float wv = wreg[jj];
            a.x += wv * sjs[jj][nq * 4 + 0];
            a.y += wv * sjs[jj][nq * 4 + 1];
            a.z += wv * sjs[jj][nq * 4 + 2];
            a.w += wv * sjs[jj][nq * 4 + 3];
        }
        float4 r;
        r.x = a.x * scl + bo; r.y = a.y * scl + bo;
        r.z = a.z * scl + bo; r.w = a.w * scl + bo;
        *(float4*)&op[nq * 4] = r;
    }
}

// ---------------- launch ----------------
extern "C" void kernel_launch(void* const* d_in, const int* in_sizes, int n_in,
                              void* d_out, int out_size) {
    const float* x       = (const float*)d_in[0];
    const float* Wq      = (const float*)d_in[1];
    const float* Wk      = (const float*)d_in[2];
    const float* Wv      = (const float*)d_in[3];
    const float* rel_h   = (const float*)d_in[4];
    const float* rel_w   = (const float*)d_in[5];
    const float* agg_g1  = (const float*)d_in[6];
    const float* agg_b1  = (const float*)d_in[7];
    const float* agg_m1  = (const float*)d_in[8];
    const float* agg_v1  = (const float*)d_in[9];
    const float* agg_W   = (const float*)d_in[10];
    const float* agg_g2  = (const float*)d_in[11];
    const float* agg_b2  = (const float*)d_in[12];
    const float* agg_m2  = (const float*)d_in[13];
    const float* agg_v2  = (const float*)d_in[14];
    const float* se_Win  = (const float*)d_in[15];
    const float* se_g_in = (const float*)d_in[16];
    const float* se_b_in = (const float*)d_in[17];
    const float* se_m_in = (const float*)d_in[18];
    const float* se_v_in = (const float*)d_in[19];
    const float* se_fc1  = (const float*)d_in[20];
    const float* se_fc2  = (const float*)d_in[21];
    const float* se_Wout = (const float*)d_in[22];
    const float* se_g_out= (const float*)d_in[23];
    const float* se_b_out= (const float*)d_in[24];
    const float* se_m_out= (const float*)d_in[25];
    const float* se_v_out= (const float*)d_in[26];
    float* out = (float*)d_out;

    dim3 gqkv(NCOL / 64, CO / 64, 3);
    gemm_qkv_kernel<<<gqkv, 256>>>(Wq, Wk, Wv, x);

    attn_kernel<<<(NB * NHEAD * HW) / 8, 256>>>(rel_h, rel_w, agg_g1, agg_b1, agg_m1, agg_v1);

    dim3 gagg(NCOL / 64, CO / 64);
    gemm_agg_kernel<<<gagg, 256>>>(agg_W, agg_g2, agg_b2, agg_m2, agg_v2);

    zero_p_kernel<<<1, 64>>>();
    se1_kernel<<<NCOL / 64, 256>>>(se_Win, se_g_in, se_b_in, se_m_in, se_v_in);
    se2_kernel<<<1, 64>>>(se_fc1, se_fc2);
    se3_kernel<<<NCOL / 16, 256>>>(se_Wout, se_g_out, se_b_out, se_m_out, se_v_out, out);
}